// round 8
// baseline (speedup 1.0000x reference)
#include <cuda_runtime.h>
#include <math.h>

// Fixed problem shapes (from setup_inputs)
#define BB   8
#define TT   64
#define RR   100
#define TH   768
#define IH   1024
#define PP   512

// Scratch for intermediate q [B*T, P] and k [B*R, P]
__device__ float g_q[BB * TT * PP];
__device__ float g_k[BB * RR * PP];

typedef unsigned long long ull;

// ---------------- f32x2 helpers (Blackwell packed fp32) -----------------------
__device__ __forceinline__ ull ffma2(ull a, ull b, ull c) {
    ull d;
    asm("fma.rn.f32x2 %0, %1, %2, %3;" : "=l"(d) : "l"(a), "l"(b), "l"(c));
    return d;
}
__device__ __forceinline__ float2 unpack2(ull v) {
    float2 f;
    asm("mov.b64 {%0, %1}, %2;" : "=f"(f.x), "=f"(f.y) : "l"(v));
    return f;
}
__device__ __forceinline__ ull dup2(float x) {
    ull r;
    asm("mov.b64 %0, {%1, %1};" : "=l"(r) : "f"(x));
    return r;
}

__device__ __forceinline__ float gelu_exact(float x) {
    return 0.5f * x * (1.0f + erff(x * 0.70710678118654752440f));
}

__device__ __forceinline__ float tanh_approx(float x) {
    float y;
    asm("tanh.approx.f32 %0, %1;" : "=f"(y) : "f"(x));
    return y;
}

// ---------------- Kernel 1: fused GEMM + bias + exact GELU --------------------
// blocks [0,128)   : q = gelu(encT[512,768] @ Wq + bq) -> g_q   (16 x 8 tiles)
// blocks [128,328) : k = gelu(encI[800,1024] @ Wk + bk) -> g_k  (25 x 8 tiles)
// Block tile 32(M) x 64(N) x 32(K), 128 threads, per-thread 4x4 microtile.
// A tile transposed (f32x2 row-pairs come pre-packed); W tile DUPLICATED
// ({b,b} ulonglongs) so the b operand of ffma2 needs no splat MOVs.
// Inner kk: 3x LDS.128 + 8x FFMA2 = 11 instrs for 16 FMA-cycles.
#define GBM 32
#define GBN 64
#define GBK 32

__global__ __launch_bounds__(128) void gemm_gelu_kernel(
    const float* __restrict__ encT, const float* __restrict__ Wq,
    const float* __restrict__ bq,
    const float* __restrict__ encI, const float* __restrict__ Wk,
    const float* __restrict__ bk)
{
    __shared__ __align__(16) float Ast[2][GBK][GBM + 4];   // transposed, pad->stride 36
    __shared__ __align__(16) ull   Wd[2][GBK][GBN];        // duplicated pairs

    int bid = blockIdx.x;
    const float* A; const float* W; const float* bias; float* C;
    int K, mt, nt;
    if (bid < 128) {
        A = encT; W = Wq; bias = bq; C = g_q; K = TH;
        mt = bid >> 3; nt = bid & 7;
    } else {
        bid -= 128;
        A = encI; W = Wk; bias = bk; C = g_k; K = IH;
        mt = bid >> 3; nt = bid & 7;      // mt in [0,25): 800 rows exact
    }
    const int m0 = mt * GBM;
    const int n0 = nt * GBN;

    const int tid = threadIdx.x;
    const int tx = tid & 15;    // cols tx*4 .. tx*4+3
    const int ty = tid >> 4;    // rows ty*4 .. ty*4+3

    // A loader: 2 phases, flat = ph*512 + tid*4 -> r = flat>>5, c = flat&31
    const int ar0 = (tid * 4) >> 5,          ac = (tid * 4) & 31;
    const int ar1 = ((512 + tid * 4) >> 5);
    // W loader: 4 phases, flat = ph*512 + tid*4 -> kk = flat>>6, n = flat&63
    const int wk0 = (tid * 4) >> 6,          wn = (tid * 4) & 63;

    ull a00 = 0, a01 = 0, a02 = 0, a03 = 0;   // rowpair 0 (rows ty*4+0,1), cols 0..3
    ull a10 = 0, a11 = 0, a12 = 0, a13 = 0;   // rowpair 1 (rows ty*4+2,3)

    const int niter = K / GBK;
    float4 pa0, pa1, pw0, pw1, pw2, pw3;

    // ---- prefetch + store tile 0
    {
        pa0 = *(const float4*)&A[(m0 + ar0) * K + ac];
        pa1 = *(const float4*)&A[(m0 + ar1) * K + ac];
        pw0 = *(const float4*)&W[(wk0 +  0) * PP + n0 + wn];
        pw1 = *(const float4*)&W[(wk0 +  8) * PP + n0 + wn];
        pw2 = *(const float4*)&W[(wk0 + 16) * PP + n0 + wn];
        pw3 = *(const float4*)&W[(wk0 + 24) * PP + n0 + wn];

        Ast[0][ac + 0][ar0] = pa0.x; Ast[0][ac + 1][ar0] = pa0.y;
        Ast[0][ac + 2][ar0] = pa0.z; Ast[0][ac + 3][ar0] = pa0.w;
        Ast[0][ac + 0][ar1] = pa1.x; Ast[0][ac + 1][ar1] = pa1.y;
        Ast[0][ac + 2][ar1] = pa1.z; Ast[0][ac + 3][ar1] = pa1.w;
        #define STW(buf, kk, v)                                         \
        {   ulonglong2 d0, d1;                                          \
            d0.x = dup2(v.x); d0.y = dup2(v.y);                         \
            d1.x = dup2(v.z); d1.y = dup2(v.w);                         \
            *(ulonglong2*)&Wd[buf][kk][wn]     = d0;                    \
            *(ulonglong2*)&Wd[buf][kk][wn + 2] = d1; }
        STW(0, wk0 +  0, pw0)
        STW(0, wk0 +  8, pw1)
        STW(0, wk0 + 16, pw2)
        STW(0, wk0 + 24, pw3)
    }

    for (int it = 0; it < niter; it++) {
        __syncthreads();
        const int cur = it & 1;

        const bool more = (it + 1) < niter;
        if (more) {
            const int k0 = (it + 1) * GBK;
            pa0 = *(const float4*)&A[(m0 + ar0) * K + k0 + ac];
            pa1 = *(const float4*)&A[(m0 + ar1) * K + k0 + ac];
            pw0 = *(const float4*)&W[(k0 + wk0 +  0) * PP + n0 + wn];
            pw1 = *(const float4*)&W[(k0 + wk0 +  8) * PP + n0 + wn];
            pw2 = *(const float4*)&W[(k0 + wk0 + 16) * PP + n0 + wn];
            pw3 = *(const float4*)&W[(k0 + wk0 + 24) * PP + n0 + wn];
        }

        #pragma unroll
        for (int kk = 0; kk < GBK; kk++) {
            ulonglong2 aa = *(const ulonglong2*)&Ast[cur][kk][ty * 4];
            ulonglong2 b01 = *(const ulonglong2*)&Wd[cur][kk][tx * 4];
            ulonglong2 b23 = *(const ulonglong2*)&Wd[cur][kk][tx * 4 + 2];
            a00 = ffma2(aa.x, b01.x, a00);
            a10 = ffma2(aa.y, b01.x, a10);
            a01 = ffma2(aa.x, b01.y, a01);
            a11 = ffma2(aa.y, b01.y, a11);
            a02 = ffma2(aa.x, b23.x, a02);
            a12 = ffma2(aa.y, b23.x, a12);
            a03 = ffma2(aa.x, b23.y, a03);
            a13 = ffma2(aa.y, b23.y, a13);
        }

        if (more) {
            const int nxt = cur ^ 1;
            Ast[nxt][ac + 0][ar0] = pa0.x; Ast[nxt][ac + 1][ar0] = pa0.y;
            Ast[nxt][ac + 2][ar0] = pa0.z; Ast[nxt][ac + 3][ar0] = pa0.w;
            Ast[nxt][ac + 0][ar1] = pa1.x; Ast[nxt][ac + 1][ar1] = pa1.y;
            Ast[nxt][ac + 2][ar1] = pa1.z; Ast[nxt][ac + 3][ar1] = pa1.w;
            STW(nxt, wk0 +  0, pw0)
            STW(nxt, wk0 +  8, pw1)
            STW(nxt, wk0 + 16, pw2)
            STW(nxt, wk0 + 24, pw3)
        }
    }

    // ---- epilogue: bias + exact GELU, one float4 store per row
    float2 c00 = unpack2(a00), c01 = unpack2(a01), c02 = unpack2(a02), c03 = unpack2(a03);
    float2 c10 = unpack2(a10), c11 = unpack2(a11), c12 = unpack2(a12), c13 = unpack2(a13);
    const float4 bz = *(const float4*)&bias[n0 + tx * 4];

    const int base = (m0 + ty * 4) * PP + n0 + tx * 4;
    float4 o;
    o.x = gelu_exact(c00.x + bz.x); o.y = gelu_exact(c01.x + bz.y);
    o.z = gelu_exact(c02.x + bz.z); o.w = gelu_exact(c03.x + bz.w);
    *(float4*)&C[base] = o;
    o.x = gelu_exact(c00.y + bz.x); o.y = gelu_exact(c01.y + bz.y);
    o.z = gelu_exact(c02.y + bz.z); o.w = gelu_exact(c03.y + bz.w);
    *(float4*)&C[base + PP] = o;
    o.x = gelu_exact(c10.x + bz.x); o.y = gelu_exact(c11.x + bz.y);
    o.z = gelu_exact(c12.x + bz.z); o.w = gelu_exact(c13.x + bz.w);
    *(float4*)&C[base + 2 * PP] = o;
    o.x = gelu_exact(c10.y + bz.x); o.y = gelu_exact(c11.y + bz.y);
    o.z = gelu_exact(c12.y + bz.z); o.w = gelu_exact(c13.y + bz.w);
    *(float4*)&C[base + 3 * PP] = o;
}

// ---------------- Kernel 2: fusion + tanh + weighted reduce -------------------
// grid = B*T = 512 blocks, 256 threads (8 warps). One (b,t) per block.
// q row + w in registers; k rows software-pipelined one r ahead per warp.
// tanh.approx.f32: single MUFU op (abs err ~6e-4 per element; propagated
// logit rel err ~3e-4 < 1e-3 gate).
__global__ __launch_bounds__(256) void fusion_kernel(
    const float* __restrict__ mask, const float* __restrict__ w,
    const float* __restrict__ bptr, float* __restrict__ out)
{
    const int b = blockIdx.x >> 6;          // /TT
    const int t = blockIdx.x & 63;          // %TT
    const int warp = threadIdx.x >> 5, lane = threadIdx.x & 31;

    const float4* q4 = (const float4*)&g_q[(b * TT + t) * PP];
    const float4* w4 = (const float4*)w;
    const float4* kbase = (const float4*)&g_k[(size_t)b * RR * PP];

    float4 qv[4], wv[4];
    #pragma unroll
    for (int j = 0; j < 4; j++) {
        qv[j] = q4[lane + j * 32];
        wv[j] = w4[lane + j * 32];
    }

    const float bb = bptr[0];
    const int obase = (b * TT + t) * RR;

    float4 kv[4];
    #pragma unroll
    for (int j = 0; j < 4; j++)
        kv[j] = kbase[warp * 128 + lane + j * 32];

    for (int r = warp; r < RR; r += 8) {
        float4 nv[4];
        const int rn = r + 8;
        if (rn < RR) {
            #pragma unroll
            for (int j = 0; j < 4; j++)
                nv[j] = kbase[rn * 128 + lane + j * 32];
        }

        float acc = 0.0f;
        #pragma unroll
        for (int j = 0; j < 4; j++) {
            acc += tanh_approx(qv[j].x + kv[j].x) * wv[j].x;
            acc += tanh_approx(qv[j].y + kv[j].y) * wv[j].y;
            acc += tanh_approx(qv[j].z + kv[j].z) * wv[j].z;
            acc += tanh_approx(qv[j].w + kv[j].w) * wv[j].w;
        }
        #pragma unroll
        for (int off = 16; off; off >>= 1)
            acc += __shfl_xor_sync(0xffffffffu, acc, off);
        if (lane == 0)
            out[obase + r] = acc + bb + mask[obase + r];

        #pragma unroll
        for (int j = 0; j < 4; j++) kv[j] = nv[j];
    }
}

// ---------------- launch ------------------------------------------------------
extern "C" void kernel_launch(void* const* d_in, const int* in_sizes, int n_in,
                              void* d_out, int out_size) {
    const float* encT = (const float*)d_in[0];
    const float* encI = (const float*)d_in[1];
    const float* mask = (const float*)d_in[2];
    const float* Wq   = (const float*)d_in[3];
    const float* bq   = (const float*)d_in[4];
    const float* Wk   = (const float*)d_in[5];
    const float* bk   = (const float*)d_in[6];
    const float* w    = (const float*)d_in[7];
    const float* bp   = (const float*)d_in[8];
    float* out = (float*)d_out;

    gemm_gelu_kernel<<<328, 128>>>(encT, Wq, bq, encI, Wk, bk);
    fusion_kernel<<<BB * TT, 256>>>(mask, w, bp, out);
}

// round 9
// speedup vs baseline: 1.9432x; 1.9432x over previous
#include <cuda_runtime.h>
#include <math.h>

// Fixed problem shapes (from setup_inputs)
#define BB   8
#define TT   64
#define RR   100
#define TH   768
#define IH   1024
#define PP   512

// Scratch for intermediate q [B*T, P] and k [B*R, P]
__device__ float g_q[BB * TT * PP];
__device__ float g_k[BB * RR * PP];

typedef unsigned long long ull;

// ---------------- f32x2 helpers (Blackwell packed fp32) -----------------------
__device__ __forceinline__ ull ffma2(ull a, ull b, ull c) {
    ull d;
    asm("fma.rn.f32x2 %0, %1, %2, %3;" : "=l"(d) : "l"(a), "l"(b), "l"(c));
    return d;
}
__device__ __forceinline__ float2 unpack2(ull v) {
    float2 f;
    asm("mov.b64 {%0, %1}, %2;" : "=f"(f.x), "=f"(f.y) : "l"(v));
    return f;
}
__device__ __forceinline__ ull dup2(float x) {
    ull r;
    asm("mov.b64 %0, {%1, %1};" : "=l"(r) : "f"(x));
    return r;
}

__device__ __forceinline__ float gelu_exact(float x) {
    return 0.5f * x * (1.0f + erff(x * 0.70710678118654752440f));
}

__device__ __forceinline__ float tanh_approx(float x) {
    float y;
    asm("tanh.approx.f32 %0, %1;" : "=f"(y) : "f"(x));
    return y;
}

// ---------------- Kernel 1: fused GEMM + bias + exact GELU --------------------
// blocks [0,200)   : k = gelu(encI[800,1024] @ Wk + bk) -> g_k  (25 x 8 tiles)
// blocks [200,328) : q = gelu(encT[512,768] @ Wq + bq) -> g_q   (16 x 8 tiles)
// (k first: the partial 3rd wave then consists of the SHORT K=768 q-blocks.)
// Block tile 32(M) x 64(N) x 32(K), 128 threads, per-thread 4 rows x 4 cols.
// f32x2 packing over COLUMN pairs: B operand = raw contiguous float4 of the
// Ws row (one conflict-free LDS.128 = 2 packed col-pairs, no duplication);
// A operand = 4 row scalars (broadcast LDS.128 from transposed Ast) splatted
// via dup2. Inner kk: 2 LDS.128 + 4 MOV64 + 8 FFMA2 = 14 instr / 16 FMA-cyc.
#define GBM 32
#define GBN 64
#define GBK 32

__global__ __launch_bounds__(128) void gemm_gelu_kernel(
    const float* __restrict__ encT, const float* __restrict__ Wq,
    const float* __restrict__ bq,
    const float* __restrict__ encI, const float* __restrict__ Wk,
    const float* __restrict__ bk)
{
    __shared__ __align__(16) float Ast[2][GBK][GBM + 4];   // transposed, stride 36 (16B-aligned rows)
    __shared__ __align__(16) float Ws[2][GBK][GBN];        // raw floats

    int bid = blockIdx.x;
    const float* A; const float* W; const float* bias; float* C;
    int K, mt, nt;
    if (bid < 200) {
        A = encI; W = Wk; bias = bk; C = g_k; K = IH;
        mt = bid >> 3; nt = bid & 7;      // mt in [0,25): 800 rows exact
    } else {
        bid -= 200;
        A = encT; W = Wq; bias = bq; C = g_q; K = TH;
        mt = bid >> 3; nt = bid & 7;      // mt in [0,16)
    }
    const int m0 = mt * GBM;
    const int n0 = nt * GBN;

    const int tid = threadIdx.x;
    const int tx = tid & 15;    // cols tx*4 .. tx*4+3  (2 col-pairs)
    const int ty = tid >> 4;    // rows ty*4 .. ty*4+3

    // A loader: 2 phases of 512 floats; flat = ph*512 + tid*4
    const int ar0 = (tid * 4) >> 5,          ac = (tid * 4) & 31;
    const int ar1 = ((512 + tid * 4) >> 5);
    // W loader: 4 phases of 512 floats; flat = ph*512 + tid*4 -> kk = wk0+ph*8, n = wn
    const int wk0 = (tid * 4) >> 6;          // = tid/16
    const int wn  = (tid * 4) & 63;

    // acc[row][colpair]
    ull a00 = 0, a01 = 0, a10 = 0, a11 = 0;
    ull a20 = 0, a21 = 0, a30 = 0, a31 = 0;

    const int niter = K / GBK;
    float4 pa0, pa1, pw0, pw1, pw2, pw3;

    // ---- prefetch + store tile 0
    {
        pa0 = *(const float4*)&A[(m0 + ar0) * K + ac];
        pa1 = *(const float4*)&A[(m0 + ar1) * K + ac];
        pw0 = *(const float4*)&W[(wk0 +  0) * PP + n0 + wn];
        pw1 = *(const float4*)&W[(wk0 +  8) * PP + n0 + wn];
        pw2 = *(const float4*)&W[(wk0 + 16) * PP + n0 + wn];
        pw3 = *(const float4*)&W[(wk0 + 24) * PP + n0 + wn];

        Ast[0][ac + 0][ar0] = pa0.x; Ast[0][ac + 1][ar0] = pa0.y;
        Ast[0][ac + 2][ar0] = pa0.z; Ast[0][ac + 3][ar0] = pa0.w;
        Ast[0][ac + 0][ar1] = pa1.x; Ast[0][ac + 1][ar1] = pa1.y;
        Ast[0][ac + 2][ar1] = pa1.z; Ast[0][ac + 3][ar1] = pa1.w;
        *(float4*)&Ws[0][wk0 +  0][wn] = pw0;
        *(float4*)&Ws[0][wk0 +  8][wn] = pw1;
        *(float4*)&Ws[0][wk0 + 16][wn] = pw2;
        *(float4*)&Ws[0][wk0 + 24][wn] = pw3;
    }

    for (int it = 0; it < niter; it++) {
        __syncthreads();
        const int cur = it & 1;

        const bool more = (it + 1) < niter;
        if (more) {
            const int k0 = (it + 1) * GBK;
            pa0 = *(const float4*)&A[(m0 + ar0) * K + k0 + ac];
            pa1 = *(const float4*)&A[(m0 + ar1) * K + k0 + ac];
            pw0 = *(const float4*)&W[(k0 + wk0 +  0) * PP + n0 + wn];
            pw1 = *(const float4*)&W[(k0 + wk0 +  8) * PP + n0 + wn];
            pw2 = *(const float4*)&W[(k0 + wk0 + 16) * PP + n0 + wn];
            pw3 = *(const float4*)&W[(k0 + wk0 + 24) * PP + n0 + wn];
        }

        #pragma unroll
        for (int kk = 0; kk < GBK; kk++) {
            float4 av = *(const float4*)&Ast[cur][kk][ty * 4];      // 4 row scalars (broadcast)
            ulonglong2 bv = *(const ulonglong2*)&Ws[cur][kk][tx * 4]; // 2 packed col-pairs (contig)
            ull s0 = dup2(av.x), s1 = dup2(av.y);
            ull s2 = dup2(av.z), s3 = dup2(av.w);
            a00 = ffma2(s0, bv.x, a00);
            a01 = ffma2(s0, bv.y, a01);
            a10 = ffma2(s1, bv.x, a10);
            a11 = ffma2(s1, bv.y, a11);
            a20 = ffma2(s2, bv.x, a20);
            a21 = ffma2(s2, bv.y, a21);
            a30 = ffma2(s3, bv.x, a30);
            a31 = ffma2(s3, bv.y, a31);
        }

        if (more) {
            const int nxt = cur ^ 1;
            Ast[nxt][ac + 0][ar0] = pa0.x; Ast[nxt][ac + 1][ar0] = pa0.y;
            Ast[nxt][ac + 2][ar0] = pa0.z; Ast[nxt][ac + 3][ar0] = pa0.w;
            Ast[nxt][ac + 0][ar1] = pa1.x; Ast[nxt][ac + 1][ar1] = pa1.y;
            Ast[nxt][ac + 2][ar1] = pa1.z; Ast[nxt][ac + 3][ar1] = pa1.w;
            *(float4*)&Ws[nxt][wk0 +  0][wn] = pw0;
            *(float4*)&Ws[nxt][wk0 +  8][wn] = pw1;
            *(float4*)&Ws[nxt][wk0 + 16][wn] = pw2;
            *(float4*)&Ws[nxt][wk0 + 24][wn] = pw3;
        }
    }

    // ---- epilogue: bias + exact GELU; col-pairs unpack to adjacent cols -> float4 store
    const float4 bz = *(const float4*)&bias[n0 + tx * 4];
    const int base = (m0 + ty * 4) * PP + n0 + tx * 4;

    #define EPI_ROW(i, lo, hi, off)                                   \
    {   float2 p0 = unpack2(lo), p1 = unpack2(hi);                    \
        float4 o;                                                     \
        o.x = gelu_exact(p0.x + bz.x); o.y = gelu_exact(p0.y + bz.y); \
        o.z = gelu_exact(p1.x + bz.z); o.w = gelu_exact(p1.y + bz.w); \
        *(float4*)&C[base + (off) * PP] = o; }
    EPI_ROW(0, a00, a01, 0)
    EPI_ROW(1, a10, a11, 1)
    EPI_ROW(2, a20, a21, 2)
    EPI_ROW(3, a30, a31, 3)
}

// ---------------- Kernel 2: fusion + tanh + weighted reduce -------------------
// grid = B*T = 512 blocks, 256 threads (8 warps). One (b,t) per block.
// q row + w in registers; k rows software-pipelined one r ahead per warp.
// 4 independent accumulators break the serial FFMA dependency chain so the
// 16 MUFU.TANH per r pipeline at throughput (rt 8) instead of latency.
__global__ __launch_bounds__(256) void fusion_kernel(
    const float* __restrict__ mask, const float* __restrict__ w,
    const float* __restrict__ bptr, float* __restrict__ out)
{
    const int b = blockIdx.x >> 6;          // /TT
    const int t = blockIdx.x & 63;          // %TT
    const int warp = threadIdx.x >> 5, lane = threadIdx.x & 31;

    const float4* q4 = (const float4*)&g_q[(b * TT + t) * PP];
    const float4* w4 = (const float4*)w;
    const float4* kbase = (const float4*)&g_k[(size_t)b * RR * PP];

    float4 qv[4], wv[4];
    #pragma unroll
    for (int j = 0; j < 4; j++) {
        qv[j] = q4[lane + j * 32];
        wv[j] = w4[lane + j * 32];
    }

    const float bb = bptr[0];
    const int obase = (b * TT + t) * RR;

    float4 kv[4];
    #pragma unroll
    for (int j = 0; j < 4; j++)
        kv[j] = kbase[warp * 128 + lane + j * 32];

    for (int r = warp; r < RR; r += 8) {
        float4 nv[4];
        const int rn = r + 8;
        if (rn < RR) {
            #pragma unroll
            for (int j = 0; j < 4; j++)
                nv[j] = kbase[rn * 128 + lane + j * 32];
        }

        float ac0 = 0.0f, ac1 = 0.0f, ac2 = 0.0f, ac3 = 0.0f;
        #pragma unroll
        for (int j = 0; j < 4; j++) {
            ac0 += tanh_approx(qv[j].x + kv[j].x) * wv[j].x;
            ac1 += tanh_approx(qv[j].y + kv[j].y) * wv[j].y;
            ac2 += tanh_approx(qv[j].z + kv[j].z) * wv[j].z;
            ac3 += tanh_approx(qv[j].w + kv[j].w) * wv[j].w;
        }
        float acc = (ac0 + ac1) + (ac2 + ac3);
        #pragma unroll
        for (int off = 16; off; off >>= 1)
            acc += __shfl_xor_sync(0xffffffffu, acc, off);
        if (lane == 0)
            out[obase + r] = acc + bb + mask[obase + r];

        #pragma unroll
        for (int j = 0; j < 4; j++) kv[j] = nv[j];
    }
}

// ---------------- launch ------------------------------------------------------
extern "C" void kernel_launch(void* const* d_in, const int* in_sizes, int n_in,
                              void* d_out, int out_size) {
    const float* encT = (const float*)d_in[0];
    const float* encI = (const float*)d_in[1];
    const float* mask = (const float*)d_in[2];
    const float* Wq   = (const float*)d_in[3];
    const float* bq   = (const float*)d_in[4];
    const float* Wk   = (const float*)d_in[5];
    const float* bk   = (const float*)d_in[6];
    const float* w    = (const float*)d_in[7];
    const float* bp   = (const float*)d_in[8];
    float* out = (float*)d_out;

    gemm_gelu_kernel<<<328, 128>>>(encT, Wq, bq, encI, Wk, bk);
    fusion_kernel<<<BB * TT, 256>>>(mask, w, bp, out);
}

// round 10
// speedup vs baseline: 2.2025x; 1.1335x over previous
#include <cuda_runtime.h>
#include <math.h>

// Fixed problem shapes (from setup_inputs)
#define BB   8
#define TT   64
#define RR   100
#define TH   768
#define IH   1024
#define PP   512

// Final activations
__device__ float g_q[BB * TT * PP];          // [512][512]
__device__ float g_k[BB * RR * PP];          // [800][512]
// Split-K partial sums (half 0 | half 1)
__device__ float g_pq[2 * BB * TT * PP];
__device__ float g_pk[2 * BB * RR * PP];

typedef unsigned long long ull;

// ---------------- f32x2 helpers (Blackwell packed fp32) -----------------------
__device__ __forceinline__ ull ffma2(ull a, ull b, ull c) {
    ull d;
    asm("fma.rn.f32x2 %0, %1, %2, %3;" : "=l"(d) : "l"(a), "l"(b), "l"(c));
    return d;
}
__device__ __forceinline__ float2 unpack2(ull v) {
    float2 f;
    asm("mov.b64 {%0, %1}, %2;" : "=f"(f.x), "=f"(f.y) : "l"(v));
    return f;
}
__device__ __forceinline__ ull dup2(float x) {
    ull r;
    asm("mov.b64 %0, {%1, %1};" : "=l"(r) : "f"(x));
    return r;
}

__device__ __forceinline__ float gelu_exact(float x) {
    return 0.5f * x * (1.0f + erff(x * 0.70710678118654752440f));
}

__device__ __forceinline__ float tanh_approx(float x) {
    float y;
    asm("tanh.approx.f32 %0, %1;" : "=f"(y) : "f"(x));
    return y;
}

// ---------------- Kernel 1: split-K GEMM (raw partials) -----------------------
// blocks [0,400)   : k-GEMM encI[800,1024] @ Wk   (200 tiles x 2 K-halves)
// blocks [400,656) : q-GEMM encT[512,768]  @ Wq   (128 tiles x 2 K-halves)
// Block tile 32(M) x 64(N), K-half 512/384, 128 threads, 4 rows x 4 cols each.
// f32x2 over column pairs: B operand = contiguous conflict-free LDS.128 of the
// raw Ws row; A operand = broadcast LDS.128 of transposed Ast + dup2 splats.
// Inner kk: 2 LDS.128 + 4 MOV64 + 8 FFMA2. Raw fp32 partials to scratch.
#define GBM 32
#define GBN 64
#define GBK 32

__global__ __launch_bounds__(128) void gemm_part_kernel(
    const float* __restrict__ encT, const float* __restrict__ Wq,
    const float* __restrict__ encI, const float* __restrict__ Wk)
{
    __shared__ __align__(16) float Ast[2][GBK][GBM + 4];
    __shared__ __align__(16) float Ws[2][GBK][GBN];

    int bid = blockIdx.x;
    const float* A; const float* W; float* Cp;
    int K, niter, tile, half;
    if (bid < 400) {
        tile = bid >> 1; half = bid & 1;
        A = encI; W = Wk; K = IH; niter = IH / (2 * GBK);          // 16
        Cp = g_pk + half * (BB * RR * PP);
    } else {
        bid -= 400;
        tile = bid >> 1; half = bid & 1;
        A = encT; W = Wq; K = TH; niter = TH / (2 * GBK);          // 12
        Cp = g_pq + half * (BB * TT * PP);
    }
    const int mt = tile >> 3, nt = tile & 7;
    const int m0 = mt * GBM;
    const int n0 = nt * GBN;
    const int kbase = half * (K >> 1);

    const int tid = threadIdx.x;
    const int tx = tid & 15;    // cols tx*4 .. tx*4+3 (2 col-pairs)
    const int ty = tid >> 4;    // rows ty*4 .. ty*4+3

    const int ar0 = (tid * 4) >> 5,          ac = (tid * 4) & 31;
    const int ar1 = ((512 + tid * 4) >> 5);
    const int wk0 = (tid * 4) >> 6;
    const int wn  = (tid * 4) & 63;

    ull a00 = 0, a01 = 0, a10 = 0, a11 = 0;
    ull a20 = 0, a21 = 0, a30 = 0, a31 = 0;

    float4 pa0, pa1, pw0, pw1, pw2, pw3;

    // ---- prefetch + store tile 0
    {
        const int k0 = kbase;
        pa0 = *(const float4*)&A[(m0 + ar0) * K + k0 + ac];
        pa1 = *(const float4*)&A[(m0 + ar1) * K + k0 + ac];
        pw0 = *(const float4*)&W[(k0 + wk0 +  0) * PP + n0 + wn];
        pw1 = *(const float4*)&W[(k0 + wk0 +  8) * PP + n0 + wn];
        pw2 = *(const float4*)&W[(k0 + wk0 + 16) * PP + n0 + wn];
        pw3 = *(const float4*)&W[(k0 + wk0 + 24) * PP + n0 + wn];

        Ast[0][ac + 0][ar0] = pa0.x; Ast[0][ac + 1][ar0] = pa0.y;
        Ast[0][ac + 2][ar0] = pa0.z; Ast[0][ac + 3][ar0] = pa0.w;
        Ast[0][ac + 0][ar1] = pa1.x; Ast[0][ac + 1][ar1] = pa1.y;
        Ast[0][ac + 2][ar1] = pa1.z; Ast[0][ac + 3][ar1] = pa1.w;
        *(float4*)&Ws[0][wk0 +  0][wn] = pw0;
        *(float4*)&Ws[0][wk0 +  8][wn] = pw1;
        *(float4*)&Ws[0][wk0 + 16][wn] = pw2;
        *(float4*)&Ws[0][wk0 + 24][wn] = pw3;
    }

    for (int it = 0; it < niter; it++) {
        __syncthreads();
        const int cur = it & 1;

        const bool more = (it + 1) < niter;
        if (more) {
            const int k0 = kbase + (it + 1) * GBK;
            pa0 = *(const float4*)&A[(m0 + ar0) * K + k0 + ac];
            pa1 = *(const float4*)&A[(m0 + ar1) * K + k0 + ac];
            pw0 = *(const float4*)&W[(k0 + wk0 +  0) * PP + n0 + wn];
            pw1 = *(const float4*)&W[(k0 + wk0 +  8) * PP + n0 + wn];
            pw2 = *(const float4*)&W[(k0 + wk0 + 16) * PP + n0 + wn];
            pw3 = *(const float4*)&W[(k0 + wk0 + 24) * PP + n0 + wn];
        }

        #pragma unroll
        for (int kk = 0; kk < GBK; kk++) {
            float4 av = *(const float4*)&Ast[cur][kk][ty * 4];
            ulonglong2 bv = *(const ulonglong2*)&Ws[cur][kk][tx * 4];
            ull s0 = dup2(av.x), s1 = dup2(av.y);
            ull s2 = dup2(av.z), s3 = dup2(av.w);
            a00 = ffma2(s0, bv.x, a00);
            a01 = ffma2(s0, bv.y, a01);
            a10 = ffma2(s1, bv.x, a10);
            a11 = ffma2(s1, bv.y, a11);
            a20 = ffma2(s2, bv.x, a20);
            a21 = ffma2(s2, bv.y, a21);
            a30 = ffma2(s3, bv.x, a30);
            a31 = ffma2(s3, bv.y, a31);
        }

        if (more) {
            const int nxt = cur ^ 1;
            Ast[nxt][ac + 0][ar0] = pa0.x; Ast[nxt][ac + 1][ar0] = pa0.y;
            Ast[nxt][ac + 2][ar0] = pa0.z; Ast[nxt][ac + 3][ar0] = pa0.w;
            Ast[nxt][ac + 0][ar1] = pa1.x; Ast[nxt][ac + 1][ar1] = pa1.y;
            Ast[nxt][ac + 2][ar1] = pa1.z; Ast[nxt][ac + 3][ar1] = pa1.w;
            *(float4*)&Ws[nxt][wk0 +  0][wn] = pw0;
            *(float4*)&Ws[nxt][wk0 +  8][wn] = pw1;
            *(float4*)&Ws[nxt][wk0 + 16][wn] = pw2;
            *(float4*)&Ws[nxt][wk0 + 24][wn] = pw3;
        }
    }

    // ---- store raw partials (no bias/gelu here)
    const int base = (m0 + ty * 4) * PP + n0 + tx * 4;
    #define ST_ROW(lo, hi, off)                                       \
    {   float2 p0 = unpack2(lo), p1 = unpack2(hi);                    \
        float4 o; o.x = p0.x; o.y = p0.y; o.z = p1.x; o.w = p1.y;     \
        *(float4*)&Cp[base + (off) * PP] = o; }
    ST_ROW(a00, a01, 0)
    ST_ROW(a10, a11, 1)
    ST_ROW(a20, a21, 2)
    ST_ROW(a30, a31, 3)
}

// ---------------- Kernel 2: reduce halves + bias + exact GELU -----------------
#define QN4 (BB * TT * PP / 4)     // 65536 float4
#define KN4 (BB * RR * PP / 4)     // 102400 float4
__global__ __launch_bounds__(256) void reduce_gelu_kernel(
    const float* __restrict__ bq, const float* __restrict__ bk)
{
    int i = blockIdx.x * 256 + threadIdx.x;
    const float4 *p0, *p1, *bs; float4* dst;
    if (i < QN4) {
        p0 = (const float4*)g_pq; p1 = p0 + QN4;
        bs = (const float4*)bq;   dst = (float4*)g_q;
    } else {
        i -= QN4;
        p0 = (const float4*)g_pk; p1 = p0 + KN4;
        bs = (const float4*)bk;   dst = (float4*)g_k;
    }
    float4 a = p0[i], b = p1[i], bz = bs[i & 127];
    float4 o;
    o.x = gelu_exact(a.x + b.x + bz.x);
    o.y = gelu_exact(a.y + b.y + bz.y);
    o.z = gelu_exact(a.z + b.z + bz.z);
    o.w = gelu_exact(a.w + b.w + bz.w);
    dst[i] = o;
}

// ---------------- Kernel 3: fusion + tanh + weighted reduce -------------------
// grid = B*T = 512 blocks, 256 threads (8 warps). One (b,t) per block.
// q row + w in registers. Each warp processes r-PAIRS (r, r+8) per iteration:
// two independent accumulator sets, the two 5-level shfl reductions interleave
// so their lat-26 chains pipeline instead of serializing; 8 independent
// LDG.128 per iteration raise MLP.
__global__ __launch_bounds__(256) void fusion_kernel(
    const float* __restrict__ mask, const float* __restrict__ w,
    const float* __restrict__ bptr, float* __restrict__ out)
{
    const int b = blockIdx.x >> 6;          // /TT
    const int t = blockIdx.x & 63;          // %TT
    const int warp = threadIdx.x >> 5, lane = threadIdx.x & 31;

    const float4* q4 = (const float4*)&g_q[(b * TT + t) * PP];
    const float4* w4 = (const float4*)w;
    const float4* kbase = (const float4*)&g_k[(size_t)b * RR * PP];

    float4 qv[4], wv[4];
    #pragma unroll
    for (int j = 0; j < 4; j++) {
        qv[j] = q4[lane + j * 32];
        wv[j] = w4[lane + j * 32];
    }

    const float bb = bptr[0];
    const int obase = (b * TT + t) * RR;

    for (int j = 0; j < 7; j++) {
        const int r0 = warp + j * 16;
        const int r1 = r0 + 8;
        const bool v0 = r0 < RR, v1 = r1 < RR;

        float4 k0[4], k1[4];
        if (v0) {
            #pragma unroll
            for (int u = 0; u < 4; u++) k0[u] = kbase[r0 * 128 + lane + u * 32];
        }
        if (v1) {
            #pragma unroll
            for (int u = 0; u < 4; u++) k1[u] = kbase[r1 * 128 + lane + u * 32];
        }

        float a0 = 0.f, a1 = 0.f, a2 = 0.f, a3 = 0.f;
        float c0 = 0.f, c1 = 0.f, c2 = 0.f, c3 = 0.f;
        if (v0) {
            #pragma unroll
            for (int u = 0; u < 4; u++) {
                a0 += tanh_approx(qv[u].x + k0[u].x) * wv[u].x;
                a1 += tanh_approx(qv[u].y + k0[u].y) * wv[u].y;
                a2 += tanh_approx(qv[u].z + k0[u].z) * wv[u].z;
                a3 += tanh_approx(qv[u].w + k0[u].w) * wv[u].w;
            }
        }
        if (v1) {
            #pragma unroll
            for (int u = 0; u < 4; u++) {
                c0 += tanh_approx(qv[u].x + k1[u].x) * wv[u].x;
                c1 += tanh_approx(qv[u].y + k1[u].y) * wv[u].y;
                c2 += tanh_approx(qv[u].z + k1[u].z) * wv[u].z;
                c3 += tanh_approx(qv[u].w + k1[u].w) * wv[u].w;
            }
        }

        float s0 = (a0 + a1) + (a2 + a3);
        float s1 = (c0 + c1) + (c2 + c3);
        #pragma unroll
        for (int off = 16; off; off >>= 1) {
            s0 += __shfl_xor_sync(0xffffffffu, s0, off);
            s1 += __shfl_xor_sync(0xffffffffu, s1, off);
        }
        if (lane == 0) {
            if (v0) out[obase + r0] = s0 + bb + mask[obase + r0];
            if (v1) out[obase + r1] = s1 + bb + mask[obase + r1];
        }
    }
}

// ---------------- launch ------------------------------------------------------
extern "C" void kernel_launch(void* const* d_in, const int* in_sizes, int n_in,
                              void* d_out, int out_size) {
    const float* encT = (const float*)d_in[0];
    const float* encI = (const float*)d_in[1];
    const float* mask = (const float*)d_in[2];
    const float* Wq   = (const float*)d_in[3];
    const float* bq   = (const float*)d_in[4];
    const float* Wk   = (const float*)d_in[5];
    const float* bk   = (const float*)d_in[6];
    const float* w    = (const float*)d_in[7];
    const float* bp   = (const float*)d_in[8];
    float* out = (float*)d_out;

    gemm_part_kernel<<<656, 128>>>(encT, Wq, encI, Wk);
    reduce_gelu_kernel<<<(QN4 + KN4) / 256, 256>>>(bq, bk);
    fusion_kernel<<<BB * TT, 256>>>(mask, w, bp, out);
}

// round 11
// speedup vs baseline: 2.5064x; 1.1380x over previous
#include <cuda_runtime.h>
#include <math.h>

// Fixed problem shapes (from setup_inputs)
#define BB   8
#define TT   64
#define RR   100
#define TH   768
#define IH   1024
#define PP   512

// Final activations
__device__ float g_q[BB * TT * PP];          // [512][512]
__device__ float g_k[BB * RR * PP];          // [800][512]
// Split-K partial sums (4 K-quarters each)
__device__ float g_pq[4 * BB * TT * PP];
__device__ float g_pk[4 * BB * RR * PP];

typedef unsigned long long ull;

// ---------------- f32x2 helpers (Blackwell packed fp32) -----------------------
__device__ __forceinline__ ull ffma2(ull a, ull b, ull c) {
    ull d;
    asm("fma.rn.f32x2 %0, %1, %2, %3;" : "=l"(d) : "l"(a), "l"(b), "l"(c));
    return d;
}
__device__ __forceinline__ float2 unpack2(ull v) {
    float2 f;
    asm("mov.b64 {%0, %1}, %2;" : "=f"(f.x), "=f"(f.y) : "l"(v));
    return f;
}
__device__ __forceinline__ ull dup2(float x) {
    ull r;
    asm("mov.b64 %0, {%1, %1};" : "=l"(r) : "f"(x));
    return r;
}

__device__ __forceinline__ float gelu_exact(float x) {
    return 0.5f * x * (1.0f + erff(x * 0.70710678118654752440f));
}

__device__ __forceinline__ float tanh_approx(float x) {
    float y;
    asm("tanh.approx.f32 %0, %1;" : "=f"(y) : "f"(x));
    return y;
}

// ---------------- Kernel 1: split-K GEMM, 8x8 microtile -----------------------
// blocks [0,208)   : k-GEMM encI[800,1024] @ Wk  (13x4 tiles x 4 K-quarters)
// blocks [208,336) : q-GEMM encT[512,768]  @ Wq  ( 8x4 tiles x 4 K-quarters)
// Block tile 64(M) x 128(N) x 16(K), 128 threads, thread = 8 rows x 8 cols.
// f32x2 packed over ROW pairs: A operand = 4 ulls read directly from the
// transposed Ast (2 LDS.128, zero pack instrs); B operand = 8 scalars from
// 2 contiguous conflict-free LDS.128 of raw Ws, splatted with dup2 (reused by
// 4 FFMA2 each). Per kk: 4 LDS.128 (2048 B crossbar) vs 32 FFMA2 (16 FMA-cyc)
// -> crossbar:FMA = 1:1 (was 2:1), fma ceiling 2x higher.
#define GBM 64
#define GBN 128
#define GBK 16

__global__ __launch_bounds__(128) void gemm_part_kernel(
    const float* __restrict__ encT, const float* __restrict__ Wq,
    const float* __restrict__ encI, const float* __restrict__ Wk)
{
    __shared__ __align__(16) float Ast[2][GBK][GBM + 4];   // stride 68 (272B = 17*16, 16B-aligned rows)
    __shared__ __align__(16) float Ws[2][GBK][GBN];

    int bid = blockIdx.x;
    const float* A; const float* W; float* Cp;
    int K, Mrows, tile, half;
    if (bid < 208) {
        tile = bid >> 2; half = bid & 3;
        A = encI; W = Wk; K = IH; Mrows = BB * RR;           // 800
        Cp = g_pk + half * (BB * RR * PP);
    } else {
        bid -= 208;
        tile = bid >> 2; half = bid & 3;
        A = encT; W = Wq; K = TH; Mrows = BB * TT;           // 512
        Cp = g_pq + half * (BB * TT * PP);
    }
    const int mt = tile >> 2, nt = tile & 3;
    const int m0 = mt * GBM;
    const int n0 = nt * GBN;
    const int Kq = K >> 2;
    const int kstart = half * Kq;
    const int niter = Kq / GBK;          // k: 16, q: 12

    const int tid = threadIdx.x;
    const int tx = tid & 15;     // cols tx*8 .. +7
    const int ty = tid >> 4;     // rows ty*8 .. +7 (4 row-pairs)

    // A loader: 2 phases of 512 floats; r = tid/4 (+32), c = (tid&3)*4
    const int ar = tid >> 2;
    const int ac = (tid & 3) * 4;
    const int arow0 = min(m0 + ar,      Mrows - 1);   // clamp for 800-row tail tile
    const int arow1 = min(m0 + ar + 32, Mrows - 1);
    // W loader: 4 phases of 512 floats; kk = tid/32 (+4p), n = (tid*4)&127
    const int wk = tid >> 5;
    const int wn = (tid * 4) & 127;

    ull acc[4][8];
    #pragma unroll
    for (int i = 0; i < 4; i++)
        #pragma unroll
        for (int j = 0; j < 8; j++) acc[i][j] = 0ull;

    float4 pa0, pa1, pw0, pw1, pw2, pw3;

    #define LOAD_TILE(k0)                                            \
    {   pa0 = *(const float4*)&A[arow0 * K + (k0) + ac];             \
        pa1 = *(const float4*)&A[arow1 * K + (k0) + ac];             \
        pw0 = *(const float4*)&W[((k0) + wk +  0) * PP + n0 + wn];   \
        pw1 = *(const float4*)&W[((k0) + wk +  4) * PP + n0 + wn];   \
        pw2 = *(const float4*)&W[((k0) + wk +  8) * PP + n0 + wn];   \
        pw3 = *(const float4*)&W[((k0) + wk + 12) * PP + n0 + wn]; }

    #define STORE_TILE(buf)                                          \
    {   Ast[buf][ac + 0][ar] = pa0.x; Ast[buf][ac + 1][ar] = pa0.y;  \
        Ast[buf][ac + 2][ar] = pa0.z; Ast[buf][ac + 3][ar] = pa0.w;  \
        Ast[buf][ac + 0][ar + 32] = pa1.x;                           \
        Ast[buf][ac + 1][ar + 32] = pa1.y;                           \
        Ast[buf][ac + 2][ar + 32] = pa1.z;                           \
        Ast[buf][ac + 3][ar + 32] = pa1.w;                           \
        *(float4*)&Ws[buf][wk +  0][wn] = pw0;                       \
        *(float4*)&Ws[buf][wk +  4][wn] = pw1;                       \
        *(float4*)&Ws[buf][wk +  8][wn] = pw2;                       \
        *(float4*)&Ws[buf][wk + 12][wn] = pw3; }

    LOAD_TILE(kstart)
    STORE_TILE(0)

    for (int it = 0; it < niter; it++) {
        __syncthreads();
        const int cur = it & 1;

        const bool more = (it + 1) < niter;
        if (more) LOAD_TILE(kstart + (it + 1) * GBK)

        #pragma unroll
        for (int kk = 0; kk < GBK; kk++) {
            ulonglong2 aL = *(const ulonglong2*)&Ast[cur][kk][ty * 8];       // rowpairs 0,1
            ulonglong2 aH = *(const ulonglong2*)&Ast[cur][kk][ty * 8 + 4];   // rowpairs 2,3
            float4 b0 = *(const float4*)&Ws[cur][kk][tx * 8];
            float4 b1 = *(const float4*)&Ws[cur][kk][tx * 8 + 4];
            ull s0 = dup2(b0.x), s1 = dup2(b0.y), s2 = dup2(b0.z), s3 = dup2(b0.w);
            ull s4 = dup2(b1.x), s5 = dup2(b1.y), s6 = dup2(b1.z), s7 = dup2(b1.w);
            acc[0][0] = ffma2(aL.x, s0, acc[0][0]);
            acc[0][1] = ffma2(aL.x, s1, acc[0][1]);
            acc[0][2] = ffma2(aL.x, s2, acc[0][2]);
            acc[0][3] = ffma2(aL.x, s3, acc[0][3]);
            acc[0][4] = ffma2(aL.x, s4, acc[0][4]);
            acc[0][5] = ffma2(aL.x, s5, acc[0][5]);
            acc[0][6] = ffma2(aL.x, s6, acc[0][6]);
            acc[0][7] = ffma2(aL.x, s7, acc[0][7]);
            acc[1][0] = ffma2(aL.y, s0, acc[1][0]);
            acc[1][1] = ffma2(aL.y, s1, acc[1][1]);
            acc[1][2] = ffma2(aL.y, s2, acc[1][2]);
            acc[1][3] = ffma2(aL.y, s3, acc[1][3]);
            acc[1][4] = ffma2(aL.y, s4, acc[1][4]);
            acc[1][5] = ffma2(aL.y, s5, acc[1][5]);
            acc[1][6] = ffma2(aL.y, s6, acc[1][6]);
            acc[1][7] = ffma2(aL.y, s7, acc[1][7]);
            acc[2][0] = ffma2(aH.x, s0, acc[2][0]);
            acc[2][1] = ffma2(aH.x, s1, acc[2][1]);
            acc[2][2] = ffma2(aH.x, s2, acc[2][2]);
            acc[2][3] = ffma2(aH.x, s3, acc[2][3]);
            acc[2][4] = ffma2(aH.x, s4, acc[2][4]);
            acc[2][5] = ffma2(aH.x, s5, acc[2][5]);
            acc[2][6] = ffma2(aH.x, s6, acc[2][6]);
            acc[2][7] = ffma2(aH.x, s7, acc[2][7]);
            acc[3][0] = ffma2(aH.y, s0, acc[3][0]);
            acc[3][1] = ffma2(aH.y, s1, acc[3][1]);
            acc[3][2] = ffma2(aH.y, s2, acc[3][2]);
            acc[3][3] = ffma2(aH.y, s3, acc[3][3]);
            acc[3][4] = ffma2(aH.y, s4, acc[3][4]);
            acc[3][5] = ffma2(aH.y, s5, acc[3][5]);
            acc[3][6] = ffma2(aH.y, s6, acc[3][6]);
            acc[3][7] = ffma2(aH.y, s7, acc[3][7]);
        }

        if (more) {
            __syncthreads();
            STORE_TILE(cur ^ 1)
        }
    }

    // ---- store raw fp32 partials (guarded rows for the 800-row tail tile)
    #pragma unroll
    for (int rp = 0; rp < 4; rp++) {
        const int row0 = m0 + ty * 8 + rp * 2;
        float2 u[8];
        #pragma unroll
        for (int c = 0; c < 8; c++) u[c] = unpack2(acc[rp][c]);
        if (row0 < Mrows) {
            float4 oa = make_float4(u[0].x, u[1].x, u[2].x, u[3].x);
            float4 ob = make_float4(u[4].x, u[5].x, u[6].x, u[7].x);
            *(float4*)&Cp[row0 * PP + n0 + tx * 8]     = oa;
            *(float4*)&Cp[row0 * PP + n0 + tx * 8 + 4] = ob;
        }
        if (row0 + 1 < Mrows) {
            float4 oa = make_float4(u[0].y, u[1].y, u[2].y, u[3].y);
            float4 ob = make_float4(u[4].y, u[5].y, u[6].y, u[7].y);
            *(float4*)&Cp[(row0 + 1) * PP + n0 + tx * 8]     = oa;
            *(float4*)&Cp[(row0 + 1) * PP + n0 + tx * 8 + 4] = ob;
        }
    }
}

// ---------------- Kernel 2: reduce 4 K-quarters + bias + exact GELU -----------
#define QN4 (BB * TT * PP / 4)     // 65536 float4
#define KN4 (BB * RR * PP / 4)     // 102400 float4
__global__ __launch_bounds__(256) void reduce_gelu_kernel(
    const float* __restrict__ bq, const float* __restrict__ bk)
{
    int i = blockIdx.x * 256 + threadIdx.x;
    const float4 *p0, *bs; float4* dst; int stride;
    if (i < QN4) {
        p0 = (const float4*)g_pq; stride = QN4;
        bs = (const float4*)bq;   dst = (float4*)g_q;
    } else {
        i -= QN4;
        p0 = (const float4*)g_pk; stride = KN4;
        bs = (const float4*)bk;   dst = (float4*)g_k;
    }
    float4 a = p0[i], b = p0[i + stride];
    float4 c = p0[i + 2 * stride], d = p0[i + 3 * stride];
    float4 bz = bs[i & 127];
    float4 o;
    o.x = gelu_exact(((a.x + b.x) + (c.x + d.x)) + bz.x);
    o.y = gelu_exact(((a.y + b.y) + (c.y + d.y)) + bz.y);
    o.z = gelu_exact(((a.z + b.z) + (c.z + d.z)) + bz.z);
    o.w = gelu_exact(((a.w + b.w) + (c.w + d.w)) + bz.w);
    dst[i] = o;
}

// ---------------- Kernel 3: fusion + tanh + weighted reduce -------------------
// grid = B*T = 512 blocks, 256 threads (8 warps). One (b,t) per block.
// q row + w in registers; r-pairs per iteration with interleaved shfl chains.
__global__ __launch_bounds__(256) void fusion_kernel(
    const float* __restrict__ mask, const float* __restrict__ w,
    const float* __restrict__ bptr, float* __restrict__ out)
{
    const int b = blockIdx.x >> 6;          // /TT
    const int t = blockIdx.x & 63;          // %TT
    const int warp = threadIdx.x >> 5, lane = threadIdx.x & 31;

    const float4* q4 = (const float4*)&g_q[(b * TT + t) * PP];
    const float4* w4 = (const float4*)w;
    const float4* kbase = (const float4*)&g_k[(size_t)b * RR * PP];

    float4 qv[4], wv[4];
    #pragma unroll
    for (int j = 0; j < 4; j++) {
        qv[j] = q4[lane + j * 32];
        wv[j] = w4[lane + j * 32];
    }

    const float bb = bptr[0];
    const int obase = (b * TT + t) * RR;

    for (int j = 0; j < 7; j++) {
        const int r0 = warp + j * 16;
        const int r1 = r0 + 8;
        const bool v0 = r0 < RR, v1 = r1 < RR;

        float4 k0[4], k1[4];
        if (v0) {
            #pragma unroll
            for (int u = 0; u < 4; u++) k0[u] = kbase[r0 * 128 + lane + u * 32];
        }
        if (v1) {
            #pragma unroll
            for (int u = 0; u < 4; u++) k1[u] = kbase[r1 * 128 + lane + u * 32];
        }

        float a0 = 0.f, a1 = 0.f, a2 = 0.f, a3 = 0.f;
        float c0 = 0.f, c1 = 0.f, c2 = 0.f, c3 = 0.f;
        if (v0) {
            #pragma unroll
            for (int u = 0; u < 4; u++) {
                a0 += tanh_approx(qv[u].x + k0[u].x) * wv[u].x;
                a1 += tanh_approx(qv[u].y + k0[u].y) * wv[u].y;
                a2 += tanh_approx(qv[u].z + k0[u].z) * wv[u].z;
                a3 += tanh_approx(qv[u].w + k0[u].w) * wv[u].w;
            }
        }
        if (v1) {
            #pragma unroll
            for (int u = 0; u < 4; u++) {
                c0 += tanh_approx(qv[u].x + k1[u].x) * wv[u].x;
                c1 += tanh_approx(qv[u].y + k1[u].y) * wv[u].y;
                c2 += tanh_approx(qv[u].z + k1[u].z) * wv[u].z;
                c3 += tanh_approx(qv[u].w + k1[u].w) * wv[u].w;
            }
        }

        float s0 = (a0 + a1) + (a2 + a3);
        float s1 = (c0 + c1) + (c2 + c3);
        #pragma unroll
        for (int off = 16; off; off >>= 1) {
            s0 += __shfl_xor_sync(0xffffffffu, s0, off);
            s1 += __shfl_xor_sync(0xffffffffu, s1, off);
        }
        if (lane == 0) {
            if (v0) out[obase + r0] = s0 + bb + mask[obase + r0];
            if (v1) out[obase + r1] = s1 + bb + mask[obase + r1];
        }
    }
}

// ---------------- launch ------------------------------------------------------
extern "C" void kernel_launch(void* const* d_in, const int* in_sizes, int n_in,
                              void* d_out, int out_size) {
    const float* encT = (const float*)d_in[0];
    const float* encI = (const float*)d_in[1];
    const float* mask = (const float*)d_in[2];
    const float* Wq   = (const float*)d_in[3];
    const float* bq   = (const float*)d_in[4];
    const float* Wk   = (const float*)d_in[5];
    const float* bk   = (const float*)d_in[6];
    const float* w    = (const float*)d_in[7];
    const float* bp   = (const float*)d_in[8];
    float* out = (float*)d_out;

    gemm_part_kernel<<<336, 128>>>(encT, Wq, encI, Wk);
    reduce_gelu_kernel<<<(QN4 + KN4) / 256, 256>>>(bq, bk);
    fusion_kernel<<<BB * TT, 256>>>(mask, w, bp, out);
}

// round 13
// speedup vs baseline: 2.8150x; 1.1231x over previous
#include <cuda_runtime.h>
#include <math.h>

// Fixed problem shapes (from setup_inputs)
#define BB   8
#define TT   64
#define RR   100
#define TH   768
#define IH   1024
#define PP   512

// Final activations
__device__ float g_q[BB * TT * PP];          // [512][512]
__device__ float g_k[BB * RR * PP];          // [800][512]
// Split-K partials: uniform 128-wide K-chunks (q: 6 chunks, k: 8 chunks)
#define QSPLIT 6
#define KSPLIT 8
__device__ float g_pq[QSPLIT * BB * TT * PP];
__device__ float g_pk[KSPLIT * BB * RR * PP];

typedef unsigned long long ull;

// ---------------- f32x2 helpers (Blackwell packed fp32) -----------------------
__device__ __forceinline__ ull ffma2(ull a, ull b, ull c) {
    ull d;
    asm("fma.rn.f32x2 %0, %1, %2, %3;" : "=l"(d) : "l"(a), "l"(b), "l"(c));
    return d;
}
__device__ __forceinline__ float2 unpack2(ull v) {
    float2 f;
    asm("mov.b64 {%0, %1}, %2;" : "=f"(f.x), "=f"(f.y) : "l"(v));
    return f;
}
__device__ __forceinline__ ull dup2(float x) {
    ull r;
    asm("mov.b64 %0, {%1, %1};" : "=l"(r) : "f"(x));
    return r;
}

__device__ __forceinline__ float gelu_exact(float x) {
    return 0.5f * x * (1.0f + erff(x * 0.70710678118654752440f));
}

__device__ __forceinline__ float tanh_approx(float x) {
    float y;
    asm("tanh.approx.f32 %0, %1;" : "=f"(y) : "f"(x));
    return y;
}

// ---------------- Kernel 1: split-K GEMM, 8x8 microtile -----------------------
// Uniform K-chunk = 128 (niter = 8 for every block -> uniform wave):
//   blocks [0,416)   : k-GEMM encI[800,1024] @ Wk  (13x4 tiles x 8 chunks)
//   blocks [416,608) : q-GEMM encT[512,768]  @ Wq  ( 8x4 tiles x 6 chunks)
// 608 blocks ~ 4.1/SM (vs 2.27 before): FFMA2 rt=2 needs >2 warps/SMSP to
// cover LDS latency + barriers; this doubles resident warps with the proven
// 1:1 crossbar:FMA inner loop unchanged.
#define GBM 64
#define GBN 128
#define GBK 16
#define KCHUNK 128

__global__ __launch_bounds__(128, 4) void gemm_part_kernel(
    const float* __restrict__ encT, const float* __restrict__ Wq,
    const float* __restrict__ encI, const float* __restrict__ Wk)
{
    __shared__ __align__(16) float Ast[2][GBK][GBM + 4];   // transposed A, stride 68
    __shared__ __align__(16) float Ws[2][GBK][GBN];

    int bid = blockIdx.x;
    const float* A; const float* W; float* Cp;
    int K, Mrows, tile, half;
    if (bid < 416) {
        tile = bid >> 3; half = bid & 7;
        A = encI; W = Wk; K = IH; Mrows = BB * RR;           // 800
        Cp = g_pk + half * (BB * RR * PP);
    } else {
        bid -= 416;
        tile = bid / QSPLIT; half = bid - tile * QSPLIT;
        A = encT; W = Wq; K = TH; Mrows = BB * TT;           // 512
        Cp = g_pq + half * (BB * TT * PP);
    }
    const int mt = tile >> 2, nt = tile & 3;
    const int m0 = mt * GBM;
    const int n0 = nt * GBN;
    const int kstart = half * KCHUNK;
    const int niter = KCHUNK / GBK;      // 8, uniform

    const int tid = threadIdx.x;
    const int tx = tid & 15;     // cols tx*8 .. +7
    const int ty = tid >> 4;     // rows ty*8 .. +7 (4 row-pairs)

    // A loader: r = tid/4 (+32), c = (tid&3)*4
    const int ar = tid >> 2;
    const int ac = (tid & 3) * 4;
    const int arow0 = min(m0 + ar,      Mrows - 1);   // clamp for 800-row tail tile
    const int arow1 = min(m0 + ar + 32, Mrows - 1);
    // W loader: kk = tid/32 (+4p), n = (tid*4)&127
    const int wk = tid >> 5;
    const int wn = (tid * 4) & 127;

    ull acc[4][8];
    #pragma unroll
    for (int i = 0; i < 4; i++)
        #pragma unroll
        for (int j = 0; j < 8; j++) acc[i][j] = 0ull;

    float4 pa0, pa1, pw0, pw1, pw2, pw3;

    #define LOAD_TILE(k0)                                            \
    {   pa0 = *(const float4*)&A[arow0 * K + (k0) + ac];             \
        pa1 = *(const float4*)&A[arow1 * K + (k0) + ac];             \
        pw0 = *(const float4*)&W[((k0) + wk +  0) * PP + n0 + wn];   \
        pw1 = *(const float4*)&W[((k0) + wk +  4) * PP + n0 + wn];   \
        pw2 = *(const float4*)&W[((k0) + wk +  8) * PP + n0 + wn];   \
        pw3 = *(const float4*)&W[((k0) + wk + 12) * PP + n0 + wn]; }

    #define STORE_TILE(buf)                                          \
    {   Ast[buf][ac + 0][ar] = pa0.x; Ast[buf][ac + 1][ar] = pa0.y;  \
        Ast[buf][ac + 2][ar] = pa0.z; Ast[buf][ac + 3][ar] = pa0.w;  \
        Ast[buf][ac + 0][ar + 32] = pa1.x;                           \
        Ast[buf][ac + 1][ar + 32] = pa1.y;                           \
        Ast[buf][ac + 2][ar + 32] = pa1.z;                           \
        Ast[buf][ac + 3][ar + 32] = pa1.w;                           \
        *(float4*)&Ws[buf][wk +  0][wn] = pw0;                       \
        *(float4*)&Ws[buf][wk +  4][wn] = pw1;                       \
        *(float4*)&Ws[buf][wk +  8][wn] = pw2;                       \
        *(float4*)&Ws[buf][wk + 12][wn] = pw3; }

    LOAD_TILE(kstart)
    STORE_TILE(0)

    for (int it = 0; it < niter; it++) {
        __syncthreads();
        const int cur = it & 1;

        const bool more = (it + 1) < niter;
        if (more) LOAD_TILE(kstart + (it + 1) * GBK)

        #pragma unroll
        for (int kk = 0; kk < GBK; kk++) {
            ulonglong2 aL = *(const ulonglong2*)&Ast[cur][kk][ty * 8];       // rowpairs 0,1
            ulonglong2 aH = *(const ulonglong2*)&Ast[cur][kk][ty * 8 + 4];   // rowpairs 2,3
            float4 b0 = *(const float4*)&Ws[cur][kk][tx * 8];
            float4 b1 = *(const float4*)&Ws[cur][kk][tx * 8 + 4];
            ull s0 = dup2(b0.x), s1 = dup2(b0.y), s2 = dup2(b0.z), s3 = dup2(b0.w);
            ull s4 = dup2(b1.x), s5 = dup2(b1.y), s6 = dup2(b1.z), s7 = dup2(b1.w);
            acc[0][0] = ffma2(aL.x, s0, acc[0][0]);
            acc[0][1] = ffma2(aL.x, s1, acc[0][1]);
            acc[0][2] = ffma2(aL.x, s2, acc[0][2]);
            acc[0][3] = ffma2(aL.x, s3, acc[0][3]);
            acc[0][4] = ffma2(aL.x, s4, acc[0][4]);
            acc[0][5] = ffma2(aL.x, s5, acc[0][5]);
            acc[0][6] = ffma2(aL.x, s6, acc[0][6]);
            acc[0][7] = ffma2(aL.x, s7, acc[0][7]);
            acc[1][0] = ffma2(aL.y, s0, acc[1][0]);
            acc[1][1] = ffma2(aL.y, s1, acc[1][1]);
            acc[1][2] = ffma2(aL.y, s2, acc[1][2]);
            acc[1][3] = ffma2(aL.y, s3, acc[1][3]);
            acc[1][4] = ffma2(aL.y, s4, acc[1][4]);
            acc[1][5] = ffma2(aL.y, s5, acc[1][5]);
            acc[1][6] = ffma2(aL.y, s6, acc[1][6]);
            acc[1][7] = ffma2(aL.y, s7, acc[1][7]);
            acc[2][0] = ffma2(aH.x, s0, acc[2][0]);
            acc[2][1] = ffma2(aH.x, s1, acc[2][1]);
            acc[2][2] = ffma2(aH.x, s2, acc[2][2]);
            acc[2][3] = ffma2(aH.x, s3, acc[2][3]);
            acc[2][4] = ffma2(aH.x, s4, acc[2][4]);
            acc[2][5] = ffma2(aH.x, s5, acc[2][5]);
            acc[2][6] = ffma2(aH.x, s6, acc[2][6]);
            acc[2][7] = ffma2(aH.x, s7, acc[2][7]);
            acc[3][0] = ffma2(aH.y, s0, acc[3][0]);
            acc[3][1] = ffma2(aH.y, s1, acc[3][1]);
            acc[3][2] = ffma2(aH.y, s2, acc[3][2]);
            acc[3][3] = ffma2(aH.y, s3, acc[3][3]);
            acc[3][4] = ffma2(aH.y, s4, acc[3][4]);
            acc[3][5] = ffma2(aH.y, s5, acc[3][5]);
            acc[3][6] = ffma2(aH.y, s6, acc[3][6]);
            acc[3][7] = ffma2(aH.y, s7, acc[3][7]);
        }

        if (more) {
            __syncthreads();
            STORE_TILE(cur ^ 1)
        }
    }

    // ---- store raw fp32 partials (guarded rows for the 800-row tail tile)
    #pragma unroll
    for (int rp = 0; rp < 4; rp++) {
        const int row0 = m0 + ty * 8 + rp * 2;
        float2 u[8];
        #pragma unroll
        for (int c = 0; c < 8; c++) u[c] = unpack2(acc[rp][c]);
        if (row0 < Mrows) {
            float4 oa = make_float4(u[0].x, u[1].x, u[2].x, u[3].x);
            float4 ob = make_float4(u[4].x, u[5].x, u[6].x, u[7].x);
            *(float4*)&Cp[row0 * PP + n0 + tx * 8]     = oa;
            *(float4*)&Cp[row0 * PP + n0 + tx * 8 + 4] = ob;
        }
        if (row0 + 1 < Mrows) {
            float4 oa = make_float4(u[0].y, u[1].y, u[2].y, u[3].y);
            float4 ob = make_float4(u[4].y, u[5].y, u[6].y, u[7].y);
            *(float4*)&Cp[(row0 + 1) * PP + n0 + tx * 8]     = oa;
            *(float4*)&Cp[(row0 + 1) * PP + n0 + tx * 8 + 4] = ob;
        }
    }
}

// ---------------- Kernel 2: reduce split-K partials + bias + exact GELU -------
#define QN4 (BB * TT * PP / 4)     // 65536 float4
#define KN4 (BB * RR * PP / 4)     // 102400 float4
__global__ __launch_bounds__(256) void reduce_gelu_kernel(
    const float* __restrict__ bq, const float* __restrict__ bk)
{
    int i = blockIdx.x * 256 + threadIdx.x;
    const float4 *p0, *bs; float4* dst; int stride, nsum;
    if (i < QN4) {
        p0 = (const float4*)g_pq; stride = QN4; nsum = QSPLIT;
        bs = (const float4*)bq;   dst = (float4*)g_q;
    } else {
        i -= QN4;
        p0 = (const float4*)g_pk; stride = KN4; nsum = KSPLIT;
        bs = (const float4*)bk;   dst = (float4*)g_k;
    }
    float4 bz = bs[i & 127];
    float4 s = p0[i];
    for (int h = 1; h < nsum; h++) {
        float4 v = p0[i + h * stride];
        s.x += v.x; s.y += v.y; s.z += v.z; s.w += v.w;
    }
    float4 o;
    o.x = gelu_exact(s.x + bz.x);
    o.y = gelu_exact(s.y + bz.y);
    o.z = gelu_exact(s.z + bz.z);
    o.w = gelu_exact(s.w + bz.w);
    dst[i] = o;
}

// ---------------- Kernel 3: fusion + tanh + weighted reduce -------------------
// grid = B*T = 512 blocks, 256 threads (8 warps). One (b,t) per block.
// q row + w in registers; r-pairs per iteration with interleaved shfl chains.
__global__ __launch_bounds__(256) void fusion_kernel(
    const float* __restrict__ mask, const float* __restrict__ w,
    const float* __restrict__ bptr, float* __restrict__ out)
{
    const int b = blockIdx.x >> 6;          // /TT
    const int t = blockIdx.x & 63;          // %TT
    const int warp = threadIdx.x >> 5, lane = threadIdx.x & 31;

    const float4* q4 = (const float4*)&g_q[(b * TT + t) * PP];
    const float4* w4 = (const float4*)w;
    const float4* kbase = (const float4*)&g_k[(size_t)b * RR * PP];

    float4 qv[4], wv[4];
    #pragma unroll
    for (int j = 0; j < 4; j++) {
        qv[j] = q4[lane + j * 32];
        wv[j] = w4[lane + j * 32];
    }

    const float bb = bptr[0];
    const int obase = (b * TT + t) * RR;

    for (int j = 0; j < 7; j++) {
        const int r0 = warp + j * 16;
        const int r1 = r0 + 8;
        const bool v0 = r0 < RR, v1 = r1 < RR;

        float4 k0[4], k1[4];
        if (v0) {
            #pragma unroll
            for (int u = 0; u < 4; u++) k0[u] = kbase[r0 * 128 + lane + u * 32];
        }
        if (v1) {
            #pragma unroll
            for (int u = 0; u < 4; u++) k1[u] = kbase[r1 * 128 + lane + u * 32];
        }

        float a0 = 0.f, a1 = 0.f, a2 = 0.f, a3 = 0.f;
        float c0 = 0.f, c1 = 0.f, c2 = 0.f, c3 = 0.f;
        if (v0) {
            #pragma unroll
            for (int u = 0; u < 4; u++) {
                a0 += tanh_approx(qv[u].x + k0[u].x) * wv[u].x;
                a1 += tanh_approx(qv[u].y + k0[u].y) * wv[u].y;
                a2 += tanh_approx(qv[u].z + k0[u].z) * wv[u].z;
                a3 += tanh_approx(qv[u].w + k0[u].w) * wv[u].w;
            }
        }
        if (v1) {
            #pragma unroll
            for (int u = 0; u < 4; u++) {
                c0 += tanh_approx(qv[u].x + k1[u].x) * wv[u].x;
                c1 += tanh_approx(qv[u].y + k1[u].y) * wv[u].y;
                c2 += tanh_approx(qv[u].z + k1[u].z) * wv[u].z;
                c3 += tanh_approx(qv[u].w + k1[u].w) * wv[u].w;
            }
        }

        float s0 = (a0 + a1) + (a2 + a3);
        float s1 = (c0 + c1) + (c2 + c3);
        #pragma unroll
        for (int off = 16; off; off >>= 1) {
            s0 += __shfl_xor_sync(0xffffffffu, s0, off);
            s1 += __shfl_xor_sync(0xffffffffu, s1, off);
        }
        if (lane == 0) {
            if (v0) out[obase + r0] = s0 + bb + mask[obase + r0];
            if (v1) out[obase + r1] = s1 + bb + mask[obase + r1];
        }
    }
}

// ---------------- launch ------------------------------------------------------
extern "C" void kernel_launch(void* const* d_in, const int* in_sizes, int n_in,
                              void* d_out, int out_size) {
    const float* encT = (const float*)d_in[0];
    const float* encI = (const float*)d_in[1];
    const float* mask = (const float*)d_in[2];
    const float* Wq   = (const float*)d_in[3];
    const float* bq   = (const float*)d_in[4];
    const float* Wk   = (const float*)d_in[5];
    const float* bk   = (const float*)d_in[6];
    const float* w    = (const float*)d_in[7];
    const float* bp   = (const float*)d_in[8];
    float* out = (float*)d_out;

    gemm_part_kernel<<<416 + 32 * QSPLIT, 128>>>(encT, Wq, encI, Wk);
    reduce_gelu_kernel<<<(QN4 + KN4) / 256, 256>>>(bq, bk);
    fusion_kernel<<<BB * TT, 256>>>(mask, w, bp, out);
}